// round 13
// baseline (speedup 1.0000x reference)
#include <cuda_runtime.h>
#include <cuda_bf16.h>
#include <math.h>
#include <stdint.h>

#define E_    64
#define D_    1024
#define SMAX_ 1536
#define B_    2048
#define KTOP  4
#define NPAIR (B_ * KTOP)
#define MAXT  192

__device__ float g_h[(size_t)NPAIR * SMAX_];
__device__ float g_xr[(size_t)B_ * D_];
__device__ int   g_cnt[E_];
__device__ int   g_off[E_];
__device__ int   g_pairBK[E_ * B_];
__device__ int   g_tiles[MAXT];
__device__ int   g_ntiles;
__device__ float g_topw[B_ * KTOP];
__device__ float g_s1[E_ * SMAX_], g_sh1[E_ * SMAX_];
__device__ float g_s2[E_ * D_],    g_sh2[E_ * D_];

// ---------------- helpers ----------------
__device__ __forceinline__ uint32_t su32(const void* p) {
    uint32_t a;
    asm("{ .reg .u64 t; cvta.to.shared.u64 t, %1; cvt.u32.u64 %0, t; }" : "=r"(a) : "l"(p));
    return a;
}
__device__ __forceinline__ void cp16(uint32_t dst, const void* src) {
    asm volatile("cp.async.cg.shared.global [%0], [%1], 16;" :: "r"(dst), "l"(src) : "memory");
}
__device__ __forceinline__ void cp_commit() { asm volatile("cp.async.commit_group;" ::: "memory"); }
__device__ __forceinline__ void cp_wait1()  { asm volatile("cp.async.wait_group 1;" ::: "memory"); }
__device__ __forceinline__ uint32_t f2tf(float f) {
    uint32_t u; asm("cvt.rna.tf32.f32 %0, %1;" : "=r"(u) : "f"(f)); return u;
}
__device__ __forceinline__ uint32_t lds_b32(uint32_t a) {
    uint32_t u;
    asm volatile("ld.shared.b32 %0, [%1];" : "=r"(u) : "r"(a));
    return u;
}
__device__ __forceinline__ void ldm4(uint32_t* d, uint32_t a) {
    asm volatile("ldmatrix.sync.aligned.m8n8.x4.shared.b16 {%0,%1,%2,%3}, [%4];"
        : "=r"(d[0]), "=r"(d[1]), "=r"(d[2]), "=r"(d[3]) : "r"(a));
}
__device__ __forceinline__ void mma8(float* c, const uint32_t* a, const uint32_t* b) {
    asm volatile(
        "mma.sync.aligned.m16n8k8.row.col.f32.tf32.tf32.f32 "
        "{%0,%1,%2,%3}, {%4,%5,%6,%7}, {%8,%9}, {%0,%1,%2,%3};"
        : "+f"(c[0]), "+f"(c[1]), "+f"(c[2]), "+f"(c[3])
        : "r"(a[0]), "r"(a[1]), "r"(a[2]), "r"(a[3]), "r"(b[0]), "r"(b[1]));
}
__device__ __forceinline__ void red2(float* p, float a, float b) {
    asm volatile("red.global.add.v2.f32 [%0], {%1,%2};" :: "l"(p), "f"(a), "f"(b) : "memory");
}

#define STAGE_BYTES 16384u   // A: 64x32 f32 = 8KB, B: 32x64 f32 = 8KB
#define NSTAGE      3
#define SMEM_DYN    (NSTAGE * 16384 + 1024)

// ---------------- prep: BN fold + counter zero + out=x ----------------
__global__ void prep2_kernel(const float* __restrict__ x, float* __restrict__ out,
                             const float* __restrict__ b1, const float* __restrict__ g1,
                             const float* __restrict__ be1, const float* __restrict__ m1,
                             const float* __restrict__ v1,
                             const float* __restrict__ b2, const float* __restrict__ g2,
                             const float* __restrict__ be2, const float* __restrict__ m2,
                             const float* __restrict__ v2) {
    int i = blockIdx.x * blockDim.x + threadIdx.x;
    if (i < E_ * SMAX_) {
        float s = g1[i] * rsqrtf(v1[i] + 1e-5f);
        g_s1[i] = s; g_sh1[i] = (b1[i] - m1[i]) * s + be1[i];
    }
    if (i < E_ * D_) {
        float s = g2[i] * rsqrtf(v2[i] + 1e-5f);
        g_s2[i] = s; g_sh2[i] = (b2[i] - m2[i]) * s + be2[i];
    }
    if (i < E_) g_cnt[i] = 0;
    size_t xi = (size_t)i * 4;
    if (xi < (size_t)B_ * D_) {
        float4 v = *(const float4*)&x[xi];
        *(float4*)&out[xi] = v;          // residual base
    }
}

// ---------------- router: logits + top4 + scatter; writes tf32-rounded x ----------------
__global__ void router_kernel(const float* __restrict__ x,
                              const float* __restrict__ Wr,
                              const float* __restrict__ br) {
    __shared__ float xs[16][64], wrs[64][64], ls[16][64];
    int tid = threadIdx.x, b0 = blockIdx.x * 16;
    int ty = tid >> 4, tx = tid & 15;
    float a0 = 0.f, a1 = 0.f, a2 = 0.f, a3 = 0.f;
    for (int kc = 0; kc < D_; kc += 64) {
        { int li = tid * 4; int r = li >> 6; int c = li & 63;
          float4 vv = *(const float4*)&x[(size_t)(b0 + r) * D_ + kc + c];
          *(float4*)&xs[r][c] = vv;
          uint4 o; o.x = f2tf(vv.x); o.y = f2tf(vv.y); o.z = f2tf(vv.z); o.w = f2tf(vv.w);
          *(uint4*)&g_xr[(size_t)(b0 + r) * D_ + kc + c] = o; }
        #pragma unroll
        for (int j = 0; j < 4; j++) {
            int li = tid * 4 + j * 1024; int r = li >> 6; int c = li & 63;
            *(float4*)&wrs[r][c] = *(const float4*)&Wr[(size_t)(kc + r) * E_ + c];
        }
        __syncthreads();
        #pragma unroll
        for (int kk = 0; kk < 64; kk++) {
            float xv = xs[ty][kk];
            float4 w = *(float4*)&wrs[kk][tx * 4];
            a0 += xv * w.x; a1 += xv * w.y; a2 += xv * w.z; a3 += xv * w.w;
        }
        __syncthreads();
    }
    ls[ty][tx * 4 + 0] = a0 + br[tx * 4 + 0];
    ls[ty][tx * 4 + 1] = a1 + br[tx * 4 + 1];
    ls[ty][tx * 4 + 2] = a2 + br[tx * 4 + 2];
    ls[ty][tx * 4 + 3] = a3 + br[tx * 4 + 3];
    __syncthreads();
    int warp = tid >> 5, lane = tid & 31;
    for (int t = warp * 2; t < warp * 2 + 2; t++) {
        float v0 = ls[t][lane], v1 = ls[t][lane + 32];
        int i0 = lane, i1 = lane + 32;
        float tv[KTOP]; int ti[KTOP];
        #pragma unroll
        for (int k = 0; k < KTOP; k++) {
            float bv; int bi;
            if (v0 >= v1) { bv = v0; bi = i0; } else { bv = v1; bi = i1; }
            #pragma unroll
            for (int off = 16; off; off >>= 1) {
                float ov = __shfl_down_sync(0xffffffffu, bv, off);
                int   oi = __shfl_down_sync(0xffffffffu, bi, off);
                if (ov > bv || (ov == bv && oi < bi)) { bv = ov; bi = oi; }
            }
            bv = __shfl_sync(0xffffffffu, bv, 0);
            bi = __shfl_sync(0xffffffffu, bi, 0);
            tv[k] = bv; ti[k] = bi;
            if (bi == i0) v0 = -1e30f;
            if (bi == i1) v1 = -1e30f;
        }
        if (lane == 0) {
            float m = tv[0];
            float e0 = expf(tv[0] - m), e1 = expf(tv[1] - m);
            float e2 = expf(tv[2] - m), e3 = expf(tv[3] - m);
            float inv = 1.0f / (e0 + e1 + e2 + e3);
            float w4[4] = { e0 * inv, e1 * inv, e2 * inv, e3 * inv };
            int b = b0 + t;
            #pragma unroll
            for (int k = 0; k < KTOP; k++) {
                g_topw[b * KTOP + k] = w4[k];
                int ex = ti[k];
                int pos = atomicAdd(&g_cnt[ex], 1);
                g_pairBK[ex * B_ + pos] = b * KTOP + k;
            }
        }
    }
}

// Warp-parallel offsets + tile list
__global__ void offsets_kernel() {
    int lane = threadIdx.x;
    int c0 = g_cnt[lane], c1 = g_cnt[lane + 32];
    int t0 = (c0 + 63) >> 6, t1 = (c1 + 63) >> 6;
    int sc = c0, st = t0;
    #pragma unroll
    for (int off = 1; off < 32; off <<= 1) {
        int vc = __shfl_up_sync(0xffffffffu, sc, off);
        int vt = __shfl_up_sync(0xffffffffu, st, off);
        if (lane >= off) { sc += vc; st += vt; }
    }
    int tot_c = __shfl_sync(0xffffffffu, sc, 31);
    int tot_t = __shfl_sync(0xffffffffu, st, 31);
    int sc1 = c1, st1 = t1;
    #pragma unroll
    for (int off = 1; off < 32; off <<= 1) {
        int vc = __shfl_up_sync(0xffffffffu, sc1, off);
        int vt = __shfl_up_sync(0xffffffffu, st1, off);
        if (lane >= off) { sc1 += vc; st1 += vt; }
    }
    int off_c0 = sc - c0, off_t0 = st - t0;
    int off_c1 = tot_c + sc1 - c1, off_t1 = tot_t + st1 - t1;
    g_off[lane] = off_c0;
    g_off[lane + 32] = off_c1;
    for (int m = 0, j = 0; m < c0; m += 64, j++) g_tiles[off_t0 + j] = (lane << 20) | m;
    for (int m = 0, j = 0; m < c1; m += 64, j++) g_tiles[off_t1 + j] = ((lane + 32) << 20) | m;
    if (lane == 31) g_ntiles = tot_t + st1;
}

// ---------------- tf32 mma.sync grouped GEMM, 128-thread CTAs ----------------
// BM=64, BN=64, BK=32. 4 warps as 2(m) x 2(n), warp tile 32x32, m16n8k8.
// 4 CTAs/SM, each its own barrier domain -> desynchronized LDS/MMA phases.
// A smem: [64 m][32 k] f32, 128B rows, chunk swizzle c^(m&7).
// B smem: [32 k][64 n] f32, 256B rows, chunk swizzle c^((k&3)<<1).
template <int KD, int LDN, bool IS_G1>
__global__ __launch_bounds__(128, 4) void gemm_mma(const float* __restrict__ W,
                                                   float* __restrict__ out) {
    if ((int)blockIdx.y >= g_ntiles) return;
    const int tl = g_tiles[blockIdx.y];
    const int e  = tl >> 20;
    const int m0 = tl & 0xFFFFF;
    const int cnt = g_cnt[e];
    const int n0 = blockIdx.x * 64;
    const int off_e = g_off[e];

    extern __shared__ char dynsm[];
    __shared__ int   toks_s[64];
    __shared__ float wt_s[64];
    __shared__ float sc_s[64], sh_s[64];

    const int tid = threadIdx.x, wid = tid >> 5, lane = tid & 31;
    const int g = lane >> 2, t = lane & 3;
    const int wm = wid & 1, wn = wid >> 1;
    const uint32_t sbase = (su32(dynsm) + 1023u) & ~1023u;

    if (tid < 64) {
        int mi = m0 + tid;
        int bk = (mi < cnt) ? g_pairBK[e * B_ + mi] : -1;
        toks_s[tid] = bk;
        wt_s[tid] = (bk >= 0) ? g_topw[bk] : 0.f;
        const float* scp = IS_G1 ? g_s1 : g_s2;
        const float* shp = IS_G1 ? g_sh1 : g_sh2;
        sc_s[tid] = scp[e * LDN + n0 + tid];
        sh_s[tid] = shp[e * LDN + n0 + tid];
    }
    __syncthreads();

    // ---- A cp.async: 64 rows, 2 threads/row, 4 chunks (16B) each ----
    const int ar = tid >> 1, aq = tid & 1;
    const float* asrc;
    if (IS_G1) {
        int tok = toks_s[ar];
        int row = (tok >= 0) ? (tok >> 2) : 0;
        asrc = (const float*)g_xr + (size_t)row * KD + aq * 16;
    } else {
        int mi = m0 + ar;
        int row = (mi < cnt) ? (off_e + mi) : 0;
        asrc = (const float*)g_h + (size_t)row * KD + aq * 16;
    }
    uint32_t adst[4];
    #pragma unroll
    for (int j = 0; j < 4; j++)
        adst[j] = (uint32_t)ar * 128u + (uint32_t)(((aq * 4 + j) ^ (ar & 7)) << 4);

    // ---- B cp.async: 32 k-rows, 4 threads/row, 4 chunks each ----
    const int bk = tid >> 2, be4 = tid & 3;
    const float* bsrc = W + (size_t)e * KD * LDN + (size_t)bk * LDN + n0 + be4 * 16;
    uint32_t bdst[4];
    #pragma unroll
    for (int j = 0; j < 4; j++)
        bdst[j] = 8192u + (uint32_t)bk * 256u + (uint32_t)((((be4 * 4 + j) ^ ((bk & 3) << 1))) << 4);

    const int nchunk = KD / 32;

    // ---- A ldmatrix bases ----
    const int lr = lane & 7;
    const int lg8 = (lane >> 3) & 1;
    const int hh = lane >> 4;
    uint32_t a_row[2];
    #pragma unroll
    for (int mt = 0; mt < 2; mt++)
        a_row[mt] = (uint32_t)((wm * 32 + mt * 16 + lg8 * 8 + lr) * 128);

    // ---- B fragment offsets: addr = t*256 + j*1024 + swz(c)*16 + (g&3)*4, +ks*2048 ----
    uint32_t b_noff[8];
    #pragma unroll
    for (int nt = 0; nt < 2; nt++)
        #pragma unroll
        for (int j = 0; j < 2; j++) {
            uint32_t c = (uint32_t)(wn * 8 + nt * 2 + (g >> 2));
            b_noff[nt * 2 + j] = 8192u + (uint32_t)(t * 256 + j * 1024)
                               + (((c ^ (uint32_t)(t << 1))) << 4)
                               + (uint32_t)((g & 3) * 4);
        }
    // nt=2,3 reuse pattern: offsets for nt and nt+? -> need 4 nt: build all 8 (nt 0..3, j 0..1)
    uint32_t b_noff4[8];
    #pragma unroll
    for (int nt = 0; nt < 4; nt++)
        #pragma unroll
        for (int j = 0; j < 2; j++) {
            uint32_t c = (uint32_t)(wn * 8 + nt * 2 + (g >> 2));
            b_noff4[nt * 2 + j] = 8192u + (uint32_t)(t * 256 + j * 1024)
                                + (((c ^ (uint32_t)(t << 1))) << 4)
                                + (uint32_t)((g & 3) * 4);
        }

    float acc[2][4][4];
    #pragma unroll
    for (int i = 0; i < 2; i++)
        #pragma unroll
        for (int j = 0; j < 4; j++)
            #pragma unroll
            for (int q = 0; q < 4; q++) acc[i][j][q] = 0.f;

    // ---- prologue: stages 0,1 ----
    #pragma unroll
    for (int c = 0; c < 2; c++) {
        uint32_t sb = sbase + (uint32_t)c * STAGE_BYTES;
        const float* a = asrc + (size_t)c * 32;
        const float* b = bsrc + (size_t)c * 32 * LDN;
        #pragma unroll
        for (int j = 0; j < 4; j++) cp16(sb + adst[j], a + j * 4);
        #pragma unroll
        for (int j = 0; j < 4; j++) cp16(sb + bdst[j], b + j * 4);
        cp_commit();
    }

    #pragma unroll 1
    for (int c = 0; c < nchunk; c++) {
        cp_wait1();
        __syncthreads();
        const uint32_t ss = sbase + (uint32_t)(c % NSTAGE) * STAGE_BYTES;

        // ---- preload ks=0 fragments ----
        uint32_t bfr[2][8];
        #pragma unroll
        for (int q = 0; q < 8; q++)
            bfr[0][q] = lds_b32(ss + b_noff4[q]);
        uint32_t afr[2][4];
        {
            const uint32_t koff = (uint32_t)((hh ^ lr) << 4);
            ldm4(afr[0], ss + a_row[0] + koff);
            ldm4(afr[1], ss + a_row[1] + koff);
        }

        #pragma unroll
        for (int ks = 0; ks < 4; ks++) {
            const int cur = ks & 1, nxt = cur ^ 1;
            if (ks < 3) {
                const uint32_t kro = (uint32_t)((ks + 1) * 2048);
                #pragma unroll
                for (int q = 0; q < 8; q++)
                    bfr[nxt][q] = lds_b32(ss + kro + b_noff4[q]);
            }
            #pragma unroll
            for (int nt = 0; nt < 4; nt++)
                mma8(acc[0][nt], afr[0], &bfr[cur][nt * 2]);
            #pragma unroll
            for (int nt = 0; nt < 4; nt++)
                mma8(acc[1][nt], afr[1], &bfr[cur][nt * 2]);
            if (ks < 3) {
                const uint32_t koff = (uint32_t)(((2 * (ks + 1) + hh) ^ lr) << 4);
                ldm4(afr[0], ss + a_row[0] + koff);
                ldm4(afr[1], ss + a_row[1] + koff);
            }
        }

        // ---- prefetch chunk c+2 ----
        if (c + 2 < nchunk) {
            uint32_t sb = sbase + (uint32_t)((c + 2) % NSTAGE) * STAGE_BYTES;
            const float* a = asrc + (size_t)(c + 2) * 32;
            const float* b = bsrc + (size_t)(c + 2) * 32 * LDN;
            #pragma unroll
            for (int j = 0; j < 4; j++) cp16(sb + adst[j], a + j * 4);
            #pragma unroll
            for (int j = 0; j < 4; j++) cp16(sb + bdst[j], b + j * 4);
        }
        cp_commit();
    }

    // ---- epilogue ----
    // fragment n-cols: col = nt*8 + 2t within warp half; warp covers wn*... full
    #pragma unroll
    for (int mt = 0; mt < 2; mt++) {
        #pragma unroll
        for (int j2 = 0; j2 < 2; j2++) {
            int row = wm * 32 + mt * 16 + g + 8 * j2;
            int m = m0 + row;
            if (m >= cnt) continue;
            if (IS_G1) {
                float* orow = g_h + (size_t)(off_e + m) * LDN + n0;
                #pragma unroll
                for (int nt = 0; nt < 4; nt++) {
                    int col = wn * 32 + nt * 8 + 2 * t;
                    float v0 = acc[mt][nt][2 * j2 + 0] * sc_s[col]     + sh_s[col];
                    float v1 = acc[mt][nt][2 * j2 + 1] * sc_s[col + 1] + sh_s[col + 1];
                    v0 = fmaxf(v0, 0.f); v1 = fmaxf(v1, 0.f);
                    float2 o;
                    o.x = __uint_as_float(f2tf(v0));
                    o.y = __uint_as_float(f2tf(v1));
                    *(float2*)(orow + col) = o;
                }
            } else {
                int bkk = toks_s[row];
                float w = wt_s[row];
                float* orow = out + (size_t)(bkk >> 2) * LDN + n0;
                #pragma unroll
                for (int nt = 0; nt < 4; nt++) {
                    int col = wn * 32 + nt * 8 + 2 * t;
                    float v0 = acc[mt][nt][2 * j2 + 0] * sc_s[col]     + sh_s[col];
                    float v1 = acc[mt][nt][2 * j2 + 1] * sc_s[col + 1] + sh_s[col + 1];
                    red2(orow + col, w * v0, w * v1);
                }
            }
        }
    }
}

// ---------------- launch ----------------
extern "C" void kernel_launch(void* const* d_in, const int* in_sizes, int n_in,
                              void* d_out, int out_size) {
    const float* x   = (const float*)d_in[0];
    const float* W1  = (const float*)d_in[1];
    const float* b1  = (const float*)d_in[2];
    const float* g1  = (const float*)d_in[3];
    const float* be1 = (const float*)d_in[4];
    const float* m1  = (const float*)d_in[5];
    const float* v1  = (const float*)d_in[6];
    const float* W2  = (const float*)d_in[7];
    const float* b2  = (const float*)d_in[8];
    const float* g2  = (const float*)d_in[9];
    const float* be2 = (const float*)d_in[10];
    const float* m2  = (const float*)d_in[11];
    const float* v2  = (const float*)d_in[12];
    const float* Wr  = (const float*)d_in[13];
    const float* br  = (const float*)d_in[14];
    float* out = (float*)d_out;

    cudaFuncSetAttribute((const void*)gemm_mma<D_, SMAX_, true>,
                         cudaFuncAttributeMaxDynamicSharedMemorySize, SMEM_DYN);
    cudaFuncSetAttribute((const void*)gemm_mma<SMAX_, D_, false>,
                         cudaFuncAttributeMaxDynamicSharedMemorySize, SMEM_DYN);

    prep2_kernel<<<(B_ * D_) / 1024, 256>>>(x, out, b1, g1, be1, m1, v1, b2, g2, be2, m2, v2);
    router_kernel<<<B_ / 16, 256>>>(x, Wr, br);
    offsets_kernel<<<1, 32>>>();
    gemm_mma<D_, SMAX_, true><<<dim3(SMAX_ / 64, MAXT), 128, SMEM_DYN>>>(W1, out);
    gemm_mma<SMAX_, D_, false><<<dim3(D_ / 64, MAXT), 128, SMEM_DYN>>>(W2, out);
}

// round 14
// speedup vs baseline: 1.6906x; 1.6906x over previous
#include <cuda_runtime.h>
#include <cuda_bf16.h>
#include <math.h>
#include <stdint.h>

#define E_    64
#define D_    1024
#define SMAX_ 1536
#define B_    2048
#define KTOP  4
#define NPAIR (B_ * KTOP)
#define MAXT  192

__device__ float g_h[(size_t)NPAIR * SMAX_];
__device__ float g_xr[(size_t)B_ * D_];
__device__ int   g_cnt[E_];
__device__ int   g_off[E_];
__device__ int   g_pairBK[E_ * B_];
__device__ int   g_tiles[MAXT];
__device__ int   g_ntiles;
__device__ float g_topw[B_ * KTOP];
__device__ float g_s1[E_ * SMAX_], g_sh1[E_ * SMAX_];
__device__ float g_s2[E_ * D_],    g_sh2[E_ * D_];

// ---------------- helpers ----------------
__device__ __forceinline__ uint32_t su32(const void* p) {
    uint32_t a;
    asm("{ .reg .u64 t; cvta.to.shared.u64 t, %1; cvt.u32.u64 %0, t; }" : "=r"(a) : "l"(p));
    return a;
}
__device__ __forceinline__ void cp16(uint32_t dst, const void* src) {
    asm volatile("cp.async.cg.shared.global [%0], [%1], 16;" :: "r"(dst), "l"(src) : "memory");
}
__device__ __forceinline__ void cp_commit() { asm volatile("cp.async.commit_group;" ::: "memory"); }
__device__ __forceinline__ void cp_wait1()  { asm volatile("cp.async.wait_group 1;" ::: "memory"); }
__device__ __forceinline__ uint32_t f2tf(float f) {
    uint32_t u; asm("cvt.rna.tf32.f32 %0, %1;" : "=r"(u) : "f"(f)); return u;
}
__device__ __forceinline__ uint32_t lds_b32(uint32_t a) {
    uint32_t u;
    asm volatile("ld.shared.b32 %0, [%1];" : "=r"(u) : "r"(a));
    return u;
}
__device__ __forceinline__ void ldm4(uint32_t* d, uint32_t a) {
    asm volatile("ldmatrix.sync.aligned.m8n8.x4.shared.b16 {%0,%1,%2,%3}, [%4];"
        : "=r"(d[0]), "=r"(d[1]), "=r"(d[2]), "=r"(d[3]) : "r"(a));
}
__device__ __forceinline__ void mma8(float* c, const uint32_t* a, const uint32_t* b) {
    asm volatile(
        "mma.sync.aligned.m16n8k8.row.col.f32.tf32.tf32.f32 "
        "{%0,%1,%2,%3}, {%4,%5,%6,%7}, {%8,%9}, {%0,%1,%2,%3};"
        : "+f"(c[0]), "+f"(c[1]), "+f"(c[2]), "+f"(c[3])
        : "r"(a[0]), "r"(a[1]), "r"(a[2]), "r"(a[3]), "r"(b[0]), "r"(b[1]));
}
__device__ __forceinline__ void red2(float* p, float a, float b) {
    asm volatile("red.global.add.v2.f32 [%0], {%1,%2};" :: "l"(p), "f"(a), "f"(b) : "memory");
}

#define STAGE_BYTES 24576u   // A: 64x32 f32 = 8KB, B: 32x128 f32 = 16KB
#define NSTAGE      3
#define SMEM_DYN    (NSTAGE * 24576 + 1024)

// ---------------- prep: BN fold + counter zero + out=x ----------------
__global__ void prep2_kernel(const float* __restrict__ x, float* __restrict__ out,
                             const float* __restrict__ b1, const float* __restrict__ g1,
                             const float* __restrict__ be1, const float* __restrict__ m1,
                             const float* __restrict__ v1,
                             const float* __restrict__ b2, const float* __restrict__ g2,
                             const float* __restrict__ be2, const float* __restrict__ m2,
                             const float* __restrict__ v2) {
    int i = blockIdx.x * blockDim.x + threadIdx.x;
    if (i < E_ * SMAX_) {
        float s = g1[i] * rsqrtf(v1[i] + 1e-5f);
        g_s1[i] = s; g_sh1[i] = (b1[i] - m1[i]) * s + be1[i];
    }
    if (i < E_ * D_) {
        float s = g2[i] * rsqrtf(v2[i] + 1e-5f);
        g_s2[i] = s; g_sh2[i] = (b2[i] - m2[i]) * s + be2[i];
    }
    if (i < E_) g_cnt[i] = 0;
    size_t xi = (size_t)i * 4;
    if (xi < (size_t)B_ * D_) {
        float4 v = *(const float4*)&x[xi];
        *(float4*)&out[xi] = v;          // residual base
    }
}

// ---------------- router: logits + top4 + scatter; writes tf32-rounded x ----------------
__global__ void router_kernel(const float* __restrict__ x,
                              const float* __restrict__ Wr,
                              const float* __restrict__ br) {
    __shared__ float xs[16][64], wrs[64][64], ls[16][64];
    int tid = threadIdx.x, b0 = blockIdx.x * 16;
    int ty = tid >> 4, tx = tid & 15;
    float a0 = 0.f, a1 = 0.f, a2 = 0.f, a3 = 0.f;
    for (int kc = 0; kc < D_; kc += 64) {
        { int li = tid * 4; int r = li >> 6; int c = li & 63;
          float4 vv = *(const float4*)&x[(size_t)(b0 + r) * D_ + kc + c];
          *(float4*)&xs[r][c] = vv;
          uint4 o; o.x = f2tf(vv.x); o.y = f2tf(vv.y); o.z = f2tf(vv.z); o.w = f2tf(vv.w);
          *(uint4*)&g_xr[(size_t)(b0 + r) * D_ + kc + c] = o; }
        #pragma unroll
        for (int j = 0; j < 4; j++) {
            int li = tid * 4 + j * 1024; int r = li >> 6; int c = li & 63;
            *(float4*)&wrs[r][c] = *(const float4*)&Wr[(size_t)(kc + r) * E_ + c];
        }
        __syncthreads();
        #pragma unroll
        for (int kk = 0; kk < 64; kk++) {
            float xv = xs[ty][kk];
            float4 w = *(float4*)&wrs[kk][tx * 4];
            a0 += xv * w.x; a1 += xv * w.y; a2 += xv * w.z; a3 += xv * w.w;
        }
        __syncthreads();
    }
    ls[ty][tx * 4 + 0] = a0 + br[tx * 4 + 0];
    ls[ty][tx * 4 + 1] = a1 + br[tx * 4 + 1];
    ls[ty][tx * 4 + 2] = a2 + br[tx * 4 + 2];
    ls[ty][tx * 4 + 3] = a3 + br[tx * 4 + 3];
    __syncthreads();
    int warp = tid >> 5, lane = tid & 31;
    for (int t = warp * 2; t < warp * 2 + 2; t++) {
        float v0 = ls[t][lane], v1 = ls[t][lane + 32];
        int i0 = lane, i1 = lane + 32;
        float tv[KTOP]; int ti[KTOP];
        #pragma unroll
        for (int k = 0; k < KTOP; k++) {
            float bv; int bi;
            if (v0 >= v1) { bv = v0; bi = i0; } else { bv = v1; bi = i1; }
            #pragma unroll
            for (int off = 16; off; off >>= 1) {
                float ov = __shfl_down_sync(0xffffffffu, bv, off);
                int   oi = __shfl_down_sync(0xffffffffu, bi, off);
                if (ov > bv || (ov == bv && oi < bi)) { bv = ov; bi = oi; }
            }
            bv = __shfl_sync(0xffffffffu, bv, 0);
            bi = __shfl_sync(0xffffffffu, bi, 0);
            tv[k] = bv; ti[k] = bi;
            if (bi == i0) v0 = -1e30f;
            if (bi == i1) v1 = -1e30f;
        }
        if (lane == 0) {
            float m = tv[0];
            float e0 = expf(tv[0] - m), e1 = expf(tv[1] - m);
            float e2 = expf(tv[2] - m), e3 = expf(tv[3] - m);
            float inv = 1.0f / (e0 + e1 + e2 + e3);
            float w4[4] = { e0 * inv, e1 * inv, e2 * inv, e3 * inv };
            int b = b0 + t;
            #pragma unroll
            for (int k = 0; k < KTOP; k++) {
                g_topw[b * KTOP + k] = w4[k];
                int ex = ti[k];
                int pos = atomicAdd(&g_cnt[ex], 1);
                g_pairBK[ex * B_ + pos] = b * KTOP + k;
            }
        }
    }
}

// Warp-parallel offsets + tile list
__global__ void offsets_kernel() {
    int lane = threadIdx.x;
    int c0 = g_cnt[lane], c1 = g_cnt[lane + 32];
    int t0 = (c0 + 63) >> 6, t1 = (c1 + 63) >> 6;
    int sc = c0, st = t0;
    #pragma unroll
    for (int off = 1; off < 32; off <<= 1) {
        int vc = __shfl_up_sync(0xffffffffu, sc, off);
        int vt = __shfl_up_sync(0xffffffffu, st, off);
        if (lane >= off) { sc += vc; st += vt; }
    }
    int tot_c = __shfl_sync(0xffffffffu, sc, 31);
    int tot_t = __shfl_sync(0xffffffffu, st, 31);
    int sc1 = c1, st1 = t1;
    #pragma unroll
    for (int off = 1; off < 32; off <<= 1) {
        int vc = __shfl_up_sync(0xffffffffu, sc1, off);
        int vt = __shfl_up_sync(0xffffffffu, st1, off);
        if (lane >= off) { sc1 += vc; st1 += vt; }
    }
    int off_c0 = sc - c0, off_t0 = st - t0;
    int off_c1 = tot_c + sc1 - c1, off_t1 = tot_t + st1 - t1;
    g_off[lane] = off_c0;
    g_off[lane + 32] = off_c1;
    for (int m = 0, j = 0; m < c0; m += 64, j++) g_tiles[off_t0 + j] = (lane << 20) | m;
    for (int m = 0, j = 0; m < c1; m += 64, j++) g_tiles[off_t1 + j] = ((lane + 32) << 20) | m;
    if (lane == 31) g_ntiles = tot_t + st1;
}

// ---------------- tf32 mma.sync grouped GEMM ----------------
// CTA tile BM=64 x BN=128 x BK=32 (same as R12). 128 threads: 4 warps 2(m)x2(n),
// warp tile 32x64 (acc 64 regs) -> A smem amp x2 (was x4), 2x MMA train per warp.
// A smem: [64 m][32 k] f32, 128B rows, chunk swizzle c^(m&7). (two-pass R12 store map)
// B smem: [32 k][128 n] f32, 512B rows, chunk swizzle c^((k&3)<<1). (two-pass store map)
template <int KD, int LDN, bool IS_G1>
__global__ __launch_bounds__(128, 3) void gemm_mma(const float* __restrict__ W,
                                                   float* __restrict__ out) {
    if ((int)blockIdx.y >= g_ntiles) return;
    const int tl = g_tiles[blockIdx.y];
    const int e  = tl >> 20;
    const int m0 = tl & 0xFFFFF;
    const int cnt = g_cnt[e];
    const int n0 = blockIdx.x * 128;
    const int off_e = g_off[e];

    extern __shared__ char dynsm[];
    __shared__ int   toks_s[64];
    __shared__ float wt_s[64];
    __shared__ float sc_s[128], sh_s[128];

    const int tid = threadIdx.x, wid = tid >> 5, lane = tid & 31;
    const int g = lane >> 2, t = lane & 3;
    const int wm = wid & 1, wn = wid >> 1;   // 2m x 2n warps
    const uint32_t sbase = (su32(dynsm) + 1023u) & ~1023u;

    if (tid < 64) {
        int mi = m0 + tid;
        int bk = (mi < cnt) ? g_pairBK[e * B_ + mi] : -1;
        toks_s[tid] = bk;
        wt_s[tid] = (bk >= 0) ? g_topw[bk] : 0.f;
    }
    {
        const float* scp = IS_G1 ? g_s1 : g_s2;
        const float* shp = IS_G1 ? g_sh1 : g_sh2;
        sc_s[tid] = scp[e * LDN + n0 + tid];
        sh_s[tid] = shp[e * LDN + n0 + tid];
    }
    __syncthreads();

    // ---- A cp.async: rows ar and ar+32; 4 threads/row, 2 chunks each (R12 map, 2 passes) ----
    const int ar = tid >> 2, aq = tid & 3;
    const float *asrc0, *asrc1;
    if (IS_G1) {
        int t0k = toks_s[ar], t1k = toks_s[ar + 32];
        asrc0 = (const float*)g_xr + (size_t)((t0k >= 0) ? (t0k >> 2) : 0) * KD + aq * 4;
        asrc1 = (const float*)g_xr + (size_t)((t1k >= 0) ? (t1k >> 2) : 0) * KD + aq * 4;
    } else {
        int r0 = (m0 + ar < cnt) ? (off_e + m0 + ar) : 0;
        int r1 = (m0 + ar + 32 < cnt) ? (off_e + m0 + ar + 32) : 0;
        asrc0 = (const float*)g_h + (size_t)r0 * KD + aq * 4;
        asrc1 = (const float*)g_h + (size_t)r1 * KD + aq * 4;
    }
    uint32_t adst[2];
    #pragma unroll
    for (int j = 0; j < 2; j++)
        adst[j] = (uint32_t)ar * 128u + (uint32_t)(((aq + 4 * j) ^ (ar & 7)) << 4);

    // ---- B cp.async: rows bk and bk+16; 8 threads/row, 4 chunks each (R12 map, 2 passes) ----
    const int bk = tid >> 3, be8 = tid & 7;
    const float* bsrc = W + (size_t)e * KD * LDN + (size_t)bk * LDN + n0 + be8 * 16;
    uint32_t bdst[4];
    #pragma unroll
    for (int j = 0; j < 4; j++)
        bdst[j] = 8192u + (uint32_t)bk * 512u + (uint32_t)((((be8 * 4 + j) ^ ((bk & 3) << 1))) << 4);

    const int nchunk = KD / 32;

    // ---- A ldmatrix bases ----
    const int lr = lane & 7;
    const int lg8 = (lane >> 3) & 1;
    const int hh = lane >> 4;
    uint32_t a_row[2];
    #pragma unroll
    for (int mt = 0; mt < 2; mt++)
        a_row[mt] = (uint32_t)((wm * 32 + mt * 16 + lg8 * 8 + lr) * 128);

    // ---- B fragment offsets: nt = 0..7 covers warp's 64 n-cols ----
    uint32_t b_noff[8];
    #pragma unroll
    for (int nt = 0; nt < 8; nt++) {
        uint32_t c = (uint32_t)(wn * 16 + nt * 2 + (g >> 2));
        b_noff[nt] = 8192u + (uint32_t)(t * 512 + (g & 3) * 4)
                   + ((c ^ (uint32_t)(t << 1)) << 4);
    }

    float acc[2][8][4];
    #pragma unroll
    for (int i = 0; i < 2; i++)
        #pragma unroll
        for (int j = 0; j < 8; j++)
            #pragma unroll
            for (int q = 0; q < 4; q++) acc[i][j][q] = 0.f;

    // ---- prologue: stages 0,1 ----
    #pragma unroll
    for (int c = 0; c < 2; c++) {
        uint32_t sb = sbase + (uint32_t)c * STAGE_BYTES;
        const float* a0 = asrc0 + (size_t)c * 32;
        const float* a1 = asrc1 + (size_t)c * 32;
        const float* b = bsrc + (size_t)c * 32 * LDN;
        #pragma unroll
        for (int j = 0; j < 2; j++) cp16(sb + adst[j], a0 + j * 16);
        #pragma unroll
        for (int j = 0; j < 2; j++) cp16(sb + adst[j] + 4096u, a1 + j * 16);
        #pragma unroll
        for (int j = 0; j < 4; j++) cp16(sb + bdst[j], b + j * 4);
        #pragma unroll
        for (int j = 0; j < 4; j++) cp16(sb + bdst[j] + 8192u, b + 16 * (size_t)LDN + j * 4);
        cp_commit();
    }

    #pragma unroll 1
    for (int c = 0; c < nchunk; c++) {
        cp_wait1();
        __syncthreads();
        const uint32_t ss = sbase + (uint32_t)(c % NSTAGE) * STAGE_BYTES;

        // ---- preload ks=0 fragments ----
        uint32_t bfr[2][16];
        #pragma unroll
        for (int q = 0; q < 8; q++) {
            bfr[0][q * 2 + 0] = lds_b32(ss + b_noff[q]);
            bfr[0][q * 2 + 1] = lds_b32(ss + b_noff[q] + 2048u);
        }
        uint32_t afr[2][4];
        {
            const uint32_t koff = (uint32_t)((hh ^ lr) << 4);
            ldm4(afr[0], ss + a_row[0] + koff);
            ldm4(afr[1], ss + a_row[1] + koff);
        }

        #pragma unroll
        for (int ks = 0; ks < 4; ks++) {
            const int cur = ks & 1, nxt = cur ^ 1;
            if (ks < 3) {
                const uint32_t kro = (uint32_t)((ks + 1) * 4096);
                #pragma unroll
                for (int q = 0; q < 8; q++) {
                    bfr[nxt][q * 2 + 0] = lds_b32(ss + kro + b_noff[q]);
                    bfr[nxt][q * 2 + 1] = lds_b32(ss + kro + b_noff[q] + 2048u);
                }
            }
            #pragma unroll
            for (int nt = 0; nt < 8; nt++)
                mma8(acc[0][nt], afr[0], &bfr[cur][nt * 2]);
            #pragma unroll
            for (int nt = 0; nt < 8; nt++)
                mma8(acc[1][nt], afr[1], &bfr[cur][nt * 2]);
            if (ks < 3) {
                const uint32_t koff = (uint32_t)(((2 * (ks + 1) + hh) ^ lr) << 4);
                ldm4(afr[0], ss + a_row[0] + koff);
                ldm4(afr[1], ss + a_row[1] + koff);
            }
        }

        // ---- prefetch chunk c+2 (R12-proven position) ----
        if (c + 2 < nchunk) {
            uint32_t sb = sbase + (uint32_t)((c + 2) % NSTAGE) * STAGE_BYTES;
            const float* a0 = asrc0 + (size_t)(c + 2) * 32;
            const float* a1 = asrc1 + (size_t)(c + 2) * 32;
            const float* b = bsrc + (size_t)(c + 2) * 32 * LDN;
            #pragma unroll
            for (int j = 0; j < 2; j++) cp16(sb + adst[j], a0 + j * 16);
            #pragma unroll
            for (int j = 0; j < 2; j++) cp16(sb + adst[j] + 4096u, a1 + j * 16);
            #pragma unroll
            for (int j = 0; j < 4; j++) cp16(sb + bdst[j], b + j * 4);
            #pragma unroll
            for (int j = 0; j < 4; j++) cp16(sb + bdst[j] + 8192u, b + 16 * (size_t)LDN + j * 4);
        }
        cp_commit();
    }

    // ---- epilogue ----
    #pragma unroll
    for (int mt = 0; mt < 2; mt++) {
        #pragma unroll
        for (int j2 = 0; j2 < 2; j2++) {
            int row = wm * 32 + mt * 16 + g + 8 * j2;
            int m = m0 + row;
            if (m >= cnt) continue;
            if (IS_G1) {
                float* orow = g_h + (size_t)(off_e + m) * LDN + n0;
                #pragma unroll
                for (int nt = 0; nt < 8; nt++) {
                    int col = wn * 64 + nt * 8 + 2 * t;
                    float v0 = acc[mt][nt][2 * j2 + 0] * sc_s[col]     + sh_s[col];
                    float v1 = acc[mt][nt][2 * j2 + 1] * sc_s[col + 1] + sh_s[col + 1];
                    v0 = fmaxf(v0, 0.f); v1 = fmaxf(v1, 0.f);
                    float2 o;
                    o.x = __uint_as_float(f2tf(v0));
                    o.y = __uint_as_float(f2tf(v1));
                    *(float2*)(orow + col) = o;
                }
            } else {
                int bkk = toks_s[row];
                float w = wt_s[row];
                float* orow = out + (size_t)(bkk >> 2) * LDN + n0;
                #pragma unroll
                for (int nt = 0; nt < 8; nt++) {
                    int col = wn * 64 + nt * 8 + 2 * t;
                    float v0 = acc[mt][nt][2 * j2 + 0] * sc_s[col]     + sh_s[col];
                    float v1 = acc[mt][nt][2 * j2 + 1] * sc_s[col + 1] + sh_s[col + 1];
                    red2(orow + col, w * v0, w * v1);
                }
            }
        }
    }
}

// ---------------- launch ----------------
extern "C" void kernel_launch(void* const* d_in, const int* in_sizes, int n_in,
                              void* d_out, int out_size) {
    const float* x   = (const float*)d_in[0];
    const float* W1  = (const float*)d_in[1];
    const float* b1  = (const float*)d_in[2];
    const float* g1  = (const float*)d_in[3];
    const float* be1 = (const float*)d_in[4];
    const float* m1  = (const float*)d_in[5];
    const float* v1  = (const float*)d_in[6];
    const float* W2  = (const float*)d_in[7];
    const float* b2  = (const float*)d_in[8];
    const float* g2  = (const float*)d_in[9];
    const float* be2 = (const float*)d_in[10];
    const float* m2  = (const float*)d_in[11];
    const float* v2  = (const float*)d_in[12];
    const float* Wr  = (const float*)d_in[13];
    const float* br  = (const float*)d_in[14];
    float* out = (float*)d_out;

    cudaFuncSetAttribute((const void*)gemm_mma<D_, SMAX_, true>,
                         cudaFuncAttributeMaxDynamicSharedMemorySize, SMEM_DYN);
    cudaFuncSetAttribute((const void*)gemm_mma<SMAX_, D_, false>,
                         cudaFuncAttributeMaxDynamicSharedMemorySize, SMEM_DYN);

    prep2_kernel<<<(B_ * D_) / 1024, 256>>>(x, out, b1, g1, be1, m1, v1, b2, g2, be2, m2, v2);
    router_kernel<<<B_ / 16, 256>>>(x, Wr, br);
    offsets_kernel<<<1, 32>>>();
    gemm_mma<D_, SMAX_, true><<<dim3(SMAX_ / 128, MAXT), 128, SMEM_DYN>>>(W1, out);
    gemm_mma<SMAX_, D_, false><<<dim3(D_ / 128, MAXT), 128, SMEM_DYN>>>(W2, out);
}

// round 15
// speedup vs baseline: 2.1083x; 1.2471x over previous
#include <cuda_runtime.h>
#include <cuda_bf16.h>
#include <math.h>
#include <stdint.h>

#define E_    64
#define D_    1024
#define SMAX_ 1536
#define B_    2048
#define KTOP  4
#define NPAIR (B_ * KTOP)
#define MAXT  192

__device__ float g_h[(size_t)NPAIR * SMAX_];
__device__ float g_xr[(size_t)B_ * D_];
__device__ int   g_cnt[E_];
__device__ int   g_off[E_];
__device__ int   g_pairBK[E_ * B_];
__device__ int   g_tiles[MAXT];
__device__ int   g_ntiles;
__device__ float g_topw[B_ * KTOP];
__device__ float g_s1[E_ * SMAX_], g_sh1[E_ * SMAX_];
__device__ float g_s2[E_ * D_],    g_sh2[E_ * D_];

// ---------------- helpers ----------------
__device__ __forceinline__ uint32_t su32(const void* p) {
    uint32_t a;
    asm("{ .reg .u64 t; cvta.to.shared.u64 t, %1; cvt.u32.u64 %0, t; }" : "=r"(a) : "l"(p));
    return a;
}
__device__ __forceinline__ void cp16(uint32_t dst, const void* src) {
    asm volatile("cp.async.cg.shared.global [%0], [%1], 16;" :: "r"(dst), "l"(src) : "memory");
}
__device__ __forceinline__ void cp_commit() { asm volatile("cp.async.commit_group;" ::: "memory"); }
__device__ __forceinline__ void cp_wait1()  { asm volatile("cp.async.wait_group 1;" ::: "memory"); }
__device__ __forceinline__ uint32_t f2tf(float f) {
    uint32_t u; asm("cvt.rna.tf32.f32 %0, %1;" : "=r"(u) : "f"(f)); return u;
}
__device__ __forceinline__ uint32_t lds_b32(uint32_t a) {
    uint32_t u;
    asm volatile("ld.shared.b32 %0, [%1];" : "=r"(u) : "r"(a));
    return u;
}
__device__ __forceinline__ void ldm4(uint32_t* d, uint32_t a) {
    asm volatile("ldmatrix.sync.aligned.m8n8.x4.shared.b16 {%0,%1,%2,%3}, [%4];"
        : "=r"(d[0]), "=r"(d[1]), "=r"(d[2]), "=r"(d[3]) : "r"(a));
}
__device__ __forceinline__ void mma8(float* c, const uint32_t* a, const uint32_t* b) {
    asm volatile(
        "mma.sync.aligned.m16n8k8.row.col.f32.tf32.tf32.f32 "
        "{%0,%1,%2,%3}, {%4,%5,%6,%7}, {%8,%9}, {%0,%1,%2,%3};"
        : "+f"(c[0]), "+f"(c[1]), "+f"(c[2]), "+f"(c[3])
        : "r"(a[0]), "r"(a[1]), "r"(a[2]), "r"(a[3]), "r"(b[0]), "r"(b[1]));
}
__device__ __forceinline__ void red2(float* p, float a, float b) {
    asm volatile("red.global.add.v2.f32 [%0], {%1,%2};" :: "l"(p), "f"(a), "f"(b) : "memory");
}
// expert size, bit-exact vs python: int(1024*(0.5 + e/63))
__device__ __forceinline__ int expert_size(int e) {
    return (int)(1024.0 * (0.5 + (double)e / 63.0));
}

#define STAGE_BYTES 24576u   // A: 64x32 f32 = 8KB, B: 32x128 f32 = 16KB
#define NSTAGE      3
#define SMEM_DYN    (NSTAGE * 24576 + 1024)

// ---------------- prep: BN fold + counter zero + out=x ----------------
__global__ void prep2_kernel(const float* __restrict__ x, float* __restrict__ out,
                             const float* __restrict__ b1, const float* __restrict__ g1,
                             const float* __restrict__ be1, const float* __restrict__ m1,
                             const float* __restrict__ v1,
                             const float* __restrict__ b2, const float* __restrict__ g2,
                             const float* __restrict__ be2, const float* __restrict__ m2,
                             const float* __restrict__ v2) {
    int i = blockIdx.x * blockDim.x + threadIdx.x;
    if (i < E_ * SMAX_) {
        float s = g1[i] * rsqrtf(v1[i] + 1e-5f);
        g_s1[i] = s; g_sh1[i] = (b1[i] - m1[i]) * s + be1[i];
    }
    if (i < E_ * D_) {
        float s = g2[i] * rsqrtf(v2[i] + 1e-5f);
        g_s2[i] = s; g_sh2[i] = (b2[i] - m2[i]) * s + be2[i];
    }
    if (i < E_) g_cnt[i] = 0;
    size_t xi = (size_t)i * 4;
    if (xi < (size_t)B_ * D_) {
        float4 v = *(const float4*)&x[xi];
        *(float4*)&out[xi] = v;          // residual base
    }
}

// ---------------- router: logits + top4 + scatter; writes tf32-rounded x ----------------
__global__ void router_kernel(const float* __restrict__ x,
                              const float* __restrict__ Wr,
                              const float* __restrict__ br) {
    __shared__ float xs[16][64], wrs[64][64], ls[16][64];
    int tid = threadIdx.x, b0 = blockIdx.x * 16;
    int ty = tid >> 4, tx = tid & 15;
    float a0 = 0.f, a1 = 0.f, a2 = 0.f, a3 = 0.f;
    for (int kc = 0; kc < D_; kc += 64) {
        { int li = tid * 4; int r = li >> 6; int c = li & 63;
          float4 vv = *(const float4*)&x[(size_t)(b0 + r) * D_ + kc + c];
          *(float4*)&xs[r][c] = vv;
          uint4 o; o.x = f2tf(vv.x); o.y = f2tf(vv.y); o.z = f2tf(vv.z); o.w = f2tf(vv.w);
          *(uint4*)&g_xr[(size_t)(b0 + r) * D_ + kc + c] = o; }
        #pragma unroll
        for (int j = 0; j < 4; j++) {
            int li = tid * 4 + j * 1024; int r = li >> 6; int c = li & 63;
            *(float4*)&wrs[r][c] = *(const float4*)&Wr[(size_t)(kc + r) * E_ + c];
        }
        __syncthreads();
        #pragma unroll
        for (int kk = 0; kk < 64; kk++) {
            float xv = xs[ty][kk];
            float4 w = *(float4*)&wrs[kk][tx * 4];
            a0 += xv * w.x; a1 += xv * w.y; a2 += xv * w.z; a3 += xv * w.w;
        }
        __syncthreads();
    }
    ls[ty][tx * 4 + 0] = a0 + br[tx * 4 + 0];
    ls[ty][tx * 4 + 1] = a1 + br[tx * 4 + 1];
    ls[ty][tx * 4 + 2] = a2 + br[tx * 4 + 2];
    ls[ty][tx * 4 + 3] = a3 + br[tx * 4 + 3];
    __syncthreads();
    int warp = tid >> 5, lane = tid & 31;
    for (int t = warp * 2; t < warp * 2 + 2; t++) {
        float v0 = ls[t][lane], v1 = ls[t][lane + 32];
        int i0 = lane, i1 = lane + 32;
        float tv[KTOP]; int ti[KTOP];
        #pragma unroll
        for (int k = 0; k < KTOP; k++) {
            float bv; int bi;
            if (v0 >= v1) { bv = v0; bi = i0; } else { bv = v1; bi = i1; }
            #pragma unroll
            for (int off = 16; off; off >>= 1) {
                float ov = __shfl_down_sync(0xffffffffu, bv, off);
                int   oi = __shfl_down_sync(0xffffffffu, bi, off);
                if (ov > bv || (ov == bv && oi < bi)) { bv = ov; bi = oi; }
            }
            bv = __shfl_sync(0xffffffffu, bv, 0);
            bi = __shfl_sync(0xffffffffu, bi, 0);
            tv[k] = bv; ti[k] = bi;
            if (bi == i0) v0 = -1e30f;
            if (bi == i1) v1 = -1e30f;
        }
        if (lane == 0) {
            float m = tv[0];
            float e0 = expf(tv[0] - m), e1 = expf(tv[1] - m);
            float e2 = expf(tv[2] - m), e3 = expf(tv[3] - m);
            float inv = 1.0f / (e0 + e1 + e2 + e3);
            float w4[4] = { e0 * inv, e1 * inv, e2 * inv, e3 * inv };
            int b = b0 + t;
            #pragma unroll
            for (int k = 0; k < KTOP; k++) {
                g_topw[b * KTOP + k] = w4[k];
                int ex = ti[k];
                int pos = atomicAdd(&g_cnt[ex], 1);
                g_pairBK[ex * B_ + pos] = b * KTOP + k;
            }
        }
    }
}

// Warp-parallel offsets + tile list
__global__ void offsets_kernel() {
    int lane = threadIdx.x;
    int c0 = g_cnt[lane], c1 = g_cnt[lane + 32];
    int t0 = (c0 + 63) >> 6, t1 = (c1 + 63) >> 6;
    int sc = c0, st = t0;
    #pragma unroll
    for (int off = 1; off < 32; off <<= 1) {
        int vc = __shfl_up_sync(0xffffffffu, sc, off);
        int vt = __shfl_up_sync(0xffffffffu, st, off);
        if (lane >= off) { sc += vc; st += vt; }
    }
    int tot_c = __shfl_sync(0xffffffffu, sc, 31);
    int tot_t = __shfl_sync(0xffffffffu, st, 31);
    int sc1 = c1, st1 = t1;
    #pragma unroll
    for (int off = 1; off < 32; off <<= 1) {
        int vc = __shfl_up_sync(0xffffffffu, sc1, off);
        int vt = __shfl_up_sync(0xffffffffu, st1, off);
        if (lane >= off) { sc1 += vc; st1 += vt; }
    }
    int off_c0 = sc - c0, off_t0 = st - t0;
    int off_c1 = tot_c + sc1 - c1, off_t1 = tot_t + st1 - t1;
    g_off[lane] = off_c0;
    g_off[lane + 32] = off_c1;
    for (int m = 0, j = 0; m < c0; m += 64, j++) g_tiles[off_t0 + j] = (lane << 20) | m;
    for (int m = 0, j = 0; m < c1; m += 64, j++) g_tiles[off_t1 + j] = ((lane + 32) << 20) | m;
    if (lane == 31) g_ntiles = tot_t + st1;
}

// ---------------- tf32 mma.sync grouped GEMM (R14 core + size-aware skipping) ----------------
// CTA tile BM=64 x BN=128 x BK=32. 128 threads: 4 warps 2(m)x2(n), warp tile 32x64.
// G1: skip n-tiles with n0 >= size_e (h there is identically 0 and never read).
// G2: clamp K loop to ceil(size_e/32) chunks (h/W2 pad rows are 0).
template <int KD, int LDN, bool IS_G1>
__global__ __launch_bounds__(128, 3) void gemm_mma(const float* __restrict__ W,
                                                   float* __restrict__ out) {
    if ((int)blockIdx.y >= g_ntiles) return;
    const int tl = g_tiles[blockIdx.y];
    const int e  = tl >> 20;
    const int m0 = tl & 0xFFFFF;
    const int cnt = g_cnt[e];
    const int n0 = blockIdx.x * 128;
    const int off_e = g_off[e];
    const int se = expert_size(e);
    if (IS_G1 && n0 >= se) return;          // pad n-tile: h == 0, never read

    extern __shared__ char dynsm[];
    __shared__ int   toks_s[64];
    __shared__ float wt_s[64];
    __shared__ float sc_s[128], sh_s[128];

    const int tid = threadIdx.x, wid = tid >> 5, lane = tid & 31;
    const int g = lane >> 2, t = lane & 3;
    const int wm = wid & 1, wn = wid >> 1;   // 2m x 2n warps
    const uint32_t sbase = (su32(dynsm) + 1023u) & ~1023u;

    if (tid < 64) {
        int mi = m0 + tid;
        int bk = (mi < cnt) ? g_pairBK[e * B_ + mi] : -1;
        toks_s[tid] = bk;
        wt_s[tid] = (bk >= 0) ? g_topw[bk] : 0.f;
    }
    {
        const float* scp = IS_G1 ? g_s1 : g_s2;
        const float* shp = IS_G1 ? g_sh1 : g_sh2;
        sc_s[tid] = scp[e * LDN + n0 + tid];
        sh_s[tid] = shp[e * LDN + n0 + tid];
    }
    __syncthreads();

    // ---- A cp.async: rows ar and ar+32; 4 threads/row, 2 chunks each ----
    const int ar = tid >> 2, aq = tid & 3;
    const float *asrc0, *asrc1;
    if (IS_G1) {
        int t0k = toks_s[ar], t1k = toks_s[ar + 32];
        asrc0 = (const float*)g_xr + (size_t)((t0k >= 0) ? (t0k >> 2) : 0) * KD + aq * 4;
        asrc1 = (const float*)g_xr + (size_t)((t1k >= 0) ? (t1k >> 2) : 0) * KD + aq * 4;
    } else {
        int r0 = (m0 + ar < cnt) ? (off_e + m0 + ar) : 0;
        int r1 = (m0 + ar + 32 < cnt) ? (off_e + m0 + ar + 32) : 0;
        asrc0 = (const float*)g_h + (size_t)r0 * KD + aq * 4;
        asrc1 = (const float*)g_h + (size_t)r1 * KD + aq * 4;
    }
    uint32_t adst[2];
    #pragma unroll
    for (int j = 0; j < 2; j++)
        adst[j] = (uint32_t)ar * 128u + (uint32_t)(((aq + 4 * j) ^ (ar & 7)) << 4);

    // ---- B cp.async: rows bk and bk+16; 8 threads/row, 4 chunks each ----
    const int bk = tid >> 3, be8 = tid & 7;
    const float* bsrc = W + (size_t)e * KD * LDN + (size_t)bk * LDN + n0 + be8 * 16;
    uint32_t bdst[4];
    #pragma unroll
    for (int j = 0; j < 4; j++)
        bdst[j] = 8192u + (uint32_t)bk * 512u + (uint32_t)((((be8 * 4 + j) ^ ((bk & 3) << 1))) << 4);

    // G2: only ceil(se/32) K-chunks contribute (h and W2 pad rows are zero)
    const int nchunk = IS_G1 ? (KD / 32) : ((se + 31) >> 5);

    // ---- A ldmatrix bases ----
    const int lr = lane & 7;
    const int lg8 = (lane >> 3) & 1;
    const int hh = lane >> 4;
    uint32_t a_row[2];
    #pragma unroll
    for (int mt = 0; mt < 2; mt++)
        a_row[mt] = (uint32_t)((wm * 32 + mt * 16 + lg8 * 8 + lr) * 128);

    // ---- B fragment offsets: nt = 0..7 covers warp's 64 n-cols ----
    uint32_t b_noff[8];
    #pragma unroll
    for (int nt = 0; nt < 8; nt++) {
        uint32_t c = (uint32_t)(wn * 16 + nt * 2 + (g >> 2));
        b_noff[nt] = 8192u + (uint32_t)(t * 512 + (g & 3) * 4)
                   + ((c ^ (uint32_t)(t << 1)) << 4);
    }

    float acc[2][8][4];
    #pragma unroll
    for (int i = 0; i < 2; i++)
        #pragma unroll
        for (int j = 0; j < 8; j++)
            #pragma unroll
            for (int q = 0; q < 4; q++) acc[i][j][q] = 0.f;

    // ---- prologue: stages 0,1 (nchunk >= 16 always) ----
    #pragma unroll
    for (int c = 0; c < 2; c++) {
        uint32_t sb = sbase + (uint32_t)c * STAGE_BYTES;
        const float* a0 = asrc0 + (size_t)c * 32;
        const float* a1 = asrc1 + (size_t)c * 32;
        const float* b = bsrc + (size_t)c * 32 * LDN;
        #pragma unroll
        for (int j = 0; j < 2; j++) cp16(sb + adst[j], a0 + j * 16);
        #pragma unroll
        for (int j = 0; j < 2; j++) cp16(sb + adst[j] + 4096u, a1 + j * 16);
        #pragma unroll
        for (int j = 0; j < 4; j++) cp16(sb + bdst[j], b + j * 4);
        #pragma unroll
        for (int j = 0; j < 4; j++) cp16(sb + bdst[j] + 8192u, b + 16 * (size_t)LDN + j * 4);
        cp_commit();
    }

    #pragma unroll 1
    for (int c = 0; c < nchunk; c++) {
        cp_wait1();
        __syncthreads();
        const uint32_t ss = sbase + (uint32_t)(c % NSTAGE) * STAGE_BYTES;

        // ---- preload ks=0 fragments ----
        uint32_t bfr[2][16];
        #pragma unroll
        for (int q = 0; q < 8; q++) {
            bfr[0][q * 2 + 0] = lds_b32(ss + b_noff[q]);
            bfr[0][q * 2 + 1] = lds_b32(ss + b_noff[q] + 2048u);
        }
        uint32_t afr[2][4];
        {
            const uint32_t koff = (uint32_t)((hh ^ lr) << 4);
            ldm4(afr[0], ss + a_row[0] + koff);
            ldm4(afr[1], ss + a_row[1] + koff);
        }

        #pragma unroll
        for (int ks = 0; ks < 4; ks++) {
            const int cur = ks & 1, nxt = cur ^ 1;
            if (ks < 3) {
                const uint32_t kro = (uint32_t)((ks + 1) * 4096);
                #pragma unroll
                for (int q = 0; q < 8; q++) {
                    bfr[nxt][q * 2 + 0] = lds_b32(ss + kro + b_noff[q]);
                    bfr[nxt][q * 2 + 1] = lds_b32(ss + kro + b_noff[q] + 2048u);
                }
            }
            #pragma unroll
            for (int nt = 0; nt < 8; nt++)
                mma8(acc[0][nt], afr[0], &bfr[cur][nt * 2]);
            #pragma unroll
            for (int nt = 0; nt < 8; nt++)
                mma8(acc[1][nt], afr[1], &bfr[cur][nt * 2]);
            if (ks < 3) {
                const uint32_t koff = (uint32_t)(((2 * (ks + 1) + hh) ^ lr) << 4);
                ldm4(afr[0], ss + a_row[0] + koff);
                ldm4(afr[1], ss + a_row[1] + koff);
            }
        }

        // ---- prefetch chunk c+2 ----
        if (c + 2 < nchunk) {
            uint32_t sb = sbase + (uint32_t)((c + 2) % NSTAGE) * STAGE_BYTES;
            const float* a0 = asrc0 + (size_t)(c + 2) * 32;
            const float* a1 = asrc1 + (size_t)(c + 2) * 32;
            const float* b = bsrc + (size_t)(c + 2) * 32 * LDN;
            #pragma unroll
            for (int j = 0; j < 2; j++) cp16(sb + adst[j], a0 + j * 16);
            #pragma unroll
            for (int j = 0; j < 2; j++) cp16(sb + adst[j] + 4096u, a1 + j * 16);
            #pragma unroll
            for (int j = 0; j < 4; j++) cp16(sb + bdst[j], b + j * 4);
            #pragma unroll
            for (int j = 0; j < 4; j++) cp16(sb + bdst[j] + 8192u, b + 16 * (size_t)LDN + j * 4);
        }
        cp_commit();
    }

    // ---- epilogue ----
    #pragma unroll
    for (int mt = 0; mt < 2; mt++) {
        #pragma unroll
        for (int j2 = 0; j2 < 2; j2++) {
            int row = wm * 32 + mt * 16 + g + 8 * j2;
            int m = m0 + row;
            if (m >= cnt) continue;
            if (IS_G1) {
                float* orow = g_h + (size_t)(off_e + m) * LDN + n0;
                #pragma unroll
                for (int nt = 0; nt < 8; nt++) {
                    int col = wn * 64 + nt * 8 + 2 * t;
                    float v0 = acc[mt][nt][2 * j2 + 0] * sc_s[col]     + sh_s[col];
                    float v1 = acc[mt][nt][2 * j2 + 1] * sc_s[col + 1] + sh_s[col + 1];
                    v0 = fmaxf(v0, 0.f); v1 = fmaxf(v1, 0.f);
                    float2 o;
                    o.x = __uint_as_float(f2tf(v0));
                    o.y = __uint_as_float(f2tf(v1));
                    *(float2*)(orow + col) = o;
                }
            } else {
                int bkk = toks_s[row];
                float w = wt_s[row];
                float* orow = out + (size_t)(bkk >> 2) * LDN + n0;
                #pragma unroll
                for (int nt = 0; nt < 8; nt++) {
                    int col = wn * 64 + nt * 8 + 2 * t;
                    float v0 = acc[mt][nt][2 * j2 + 0] * sc_s[col]     + sh_s[col];
                    float v1 = acc[mt][nt][2 * j2 + 1] * sc_s[col + 1] + sh_s[col + 1];
                    red2(orow + col, w * v0, w * v1);
                }
            }
        }
    }
}

// ---------------- launch ----------------
extern "C" void kernel_launch(void* const* d_in, const int* in_sizes, int n_in,
                              void* d_out, int out_size) {
    const float* x   = (const float*)d_in[0];
    const float* W1  = (const float*)d_in[1];
    const float* b1  = (const float*)d_in[2];
    const float* g1  = (const float*)d_in[3];
    const float* be1 = (const float*)d_in[4];
    const float* m1  = (const float*)d_in[5];
    const float* v1  = (const float*)d_in[6];
    const float* W2  = (const float*)d_in[7];
    const float* b2  = (const float*)d_in[8];
    const float* g2  = (const float*)d_in[9];
    const float* be2 = (const float*)d_in[10];
    const float* m2  = (const float*)d_in[11];
    const float* v2  = (const float*)d_in[12];
    const float* Wr  = (const float*)d_in[13];
    const float* br  = (const float*)d_in[14];
    float* out = (float*)d_out;

    cudaFuncSetAttribute((const void*)gemm_mma<D_, SMAX_, true>,
                         cudaFuncAttributeMaxDynamicSharedMemorySize, SMEM_DYN);
    cudaFuncSetAttribute((const void*)gemm_mma<SMAX_, D_, false>,
                         cudaFuncAttributeMaxDynamicSharedMemorySize, SMEM_DYN);

    prep2_kernel<<<(B_ * D_) / 1024, 256>>>(x, out, b1, g1, be1, m1, v1, b2, g2, be2, m2, v2);
    router_kernel<<<B_ / 16, 256>>>(x, Wr, br);
    offsets_kernel<<<1, 32>>>();
    gemm_mma<D_, SMAX_, true><<<dim3(SMAX_ / 128, MAXT), 128, SMEM_DYN>>>(W1, out);
    gemm_mma<SMAX_, D_, false><<<dim3(D_ / 128, MAXT), 128, SMEM_DYN>>>(W2, out);
}